// round 5
// baseline (speedup 1.0000x reference)
#include <cuda_runtime.h>
#include <math.h>

#define Bq   8
#define Hq   8
#define Lq   2048
#define Dq   64
#define Uq   40
#define BH   64
#define CTXN (BH*Uq*Dq)
#define NCH  8
#define KCH  8        // k-chunks for k_M (256 rows each)

// scratch (no allocations allowed)
__device__ float  g_M[BH*Lq];
__device__ float2 g_Mp[KCH*BH*Lq];     // per-chunk (max, sum) partials
__device__ int    g_top[BH*Uq];
__device__ float  g_part[NCH*CTXN];

// ---------------------------------------------------------------------------
// Kernel 1a: per-chunk sampled-QK partials.
// Block = (chunk c, bh). K chunk (256 rows x 64 f32 = 64 KB) lives in smem;
// all 2048 l rows' samples falling in this chunk are served from smem.
// Warp = 256 l's. Per (l,chunk): ballot-select in-chunk samples -> worklist,
// then 8-lane-group gathers (bank-ideal: lane e reads float4 slots {e,e+8}).
// ---------------------------------------------------------------------------
__global__ __launch_bounds__(256) void k_Mchunk(const float* __restrict__ q,
                                                const float* __restrict__ kk,
                                                const int* __restrict__ idx) {
    extern __shared__ float4 smK[];                 // 4096 f4 = 64 KB, then wq
    int c  = blockIdx.x, bh = blockIdx.y;
    int t  = threadIdx.x, w = t >> 5, lane = t & 31;
    int g  = lane >> 3, e = lane & 7;
    int* wq = (int*)(smK + 4096) + w * Uq;
    const unsigned full = 0xffffffffu;

    // fill K chunk (coalesced)
    const float4* kg = (const float4*)(kk + ((size_t)bh*Lq + c*256)*Dq);
    #pragma unroll 4
    for (int i = t; i < 4096; i += 256) smK[i] = kg[i];
    __syncthreads();

    const float4* qb4 = (const float4*)(q + (size_t)bh*Lq*Dq);

    for (int il = 0; il < 256; ++il) {
        int l = w*256 + il;
        const int* irow = idx + l*Uq;

        int  jA  = __ldg(irow + lane);
        bool inA = (jA >> 8) == c;
        bool hasB = lane < 8;
        int  jB  = hasB ? __ldg(irow + 32 + lane) : 0;
        bool inB = hasB && ((jB >> 8) == c);

        unsigned mA = __ballot_sync(full, inA);
        unsigned mB = __ballot_sync(full, inB);
        int cntA = __popc(mA);
        int cnt  = cntA + __popc(mB);

        float gmx = -INFINITY, gsm = 0.f;
        if (cnt) {                                     // warp-uniform branch
            unsigned lm = (1u << lane) - 1u;
            if (inA) wq[__popc(mA & lm)]        = (jA & 255) << 4;  // f4 row base
            if (inB) wq[cntA + __popc(mB & lm)] = (jB & 255) << 4;
            __syncwarp(full);

            float4 qa = __ldg(qb4 + (size_t)l*16 + e);
            float4 qb = __ldg(qb4 + (size_t)l*16 + e + 8);

            for (int base = 0; base < cnt; base += 4) {
                int  sidx = base + g;
                bool val  = sidx < cnt;
                int  jw   = wq[val ? sidx : 0];
                float4 ka = smK[jw + e];
                float4 kb = smK[jw + e + 8];
                float p = qa.x*ka.x;
                p = fmaf(qa.y,ka.y,p); p = fmaf(qa.z,ka.z,p); p = fmaf(qa.w,ka.w,p);
                p = fmaf(qb.x,kb.x,p); p = fmaf(qb.y,kb.y,p);
                p = fmaf(qb.z,kb.z,p); p = fmaf(qb.w,kb.w,p);
                p += __shfl_xor_sync(full, p, 4);
                p += __shfl_xor_sync(full, p, 2);
                p += __shfl_xor_sync(full, p, 1);
                if (val) { gmx = fmaxf(gmx, p); gsm += p; }
            }
            __syncwarp(full);                          // protect wq for next il
            gmx = fmaxf(gmx, __shfl_xor_sync(full, gmx, 8));
            gsm +=            __shfl_xor_sync(full, gsm, 8);
            gmx = fmaxf(gmx, __shfl_xor_sync(full, gmx, 16));
            gsm +=            __shfl_xor_sync(full, gsm, 16);
        }
        if (lane == 0)
            g_Mp[((size_t)c*BH + bh)*Lq + l] = make_float2(gmx, gsm);
    }
}

// ---------------------------------------------------------------------------
// Kernel 1b: fold the 8 chunk partials -> M  (deterministic fixed order)
// ---------------------------------------------------------------------------
__global__ void k_Mcomb() {
    int i = blockIdx.x*256 + threadIdx.x;              // bh*Lq + l
    float mx = -INFINITY, sm = 0.f;
    #pragma unroll
    for (int cc = 0; cc < KCH; ++cc) {
        float2 pp = g_Mp[(size_t)cc*BH*Lq + i];
        mx = fmaxf(mx, pp.x); sm += pp.y;
    }
    g_M[i] = mx - sm * (1.0f / (float)Lq);
}

// ---------------------------------------------------------------------------
// Kernel 2: top-40 of M per (bh)  (unchanged)
// ---------------------------------------------------------------------------
__global__ void k_topk() {
    __shared__ float sv[Lq];
    __shared__ float rv[256];
    __shared__ int   ri[256];
    int bh = blockIdx.x, t = threadIdx.x;

    for (int i = t; i < Lq; i += 256) sv[i] = g_M[bh*Lq + i];
    __syncthreads();

    for (int r = 0; r < Uq; ++r) {
        float bv = -INFINITY; int bi = Lq;
        for (int i = t; i < Lq; i += 256) {
            float x = sv[i];
            if (x > bv || (x == bv && i < bi)) { bv = x; bi = i; }
        }
        rv[t] = bv; ri[t] = bi;
        __syncthreads();
        for (int o = 128; o > 0; o >>= 1) {
            if (t < o) {
                float x = rv[t+o]; int j = ri[t+o];
                if (x > rv[t] || (x == rv[t] && j < ri[t])) { rv[t] = x; ri[t] = j; }
            }
            __syncthreads();
        }
        if (t == 0) { g_top[bh*Uq + r] = ri[0]; sv[ri[0]] = -INFINITY; }
        __syncthreads();
    }
}

// ---------------------------------------------------------------------------
// Kernel 3: scores, 4x4 register-tiled (unchanged from R4)
// ---------------------------------------------------------------------------
__global__ __launch_bounds__(320) void k_scores(const float* __restrict__ q,
                                                const float* __restrict__ kk,
                                                float* __restrict__ attn) {
    __shared__ float qs[Uq][68];
    __shared__ float ks[128][68];
    int bh = blockIdx.y, tile = blockIdx.x, t = threadIdx.x;
    int w = t >> 5, lane = t & 31;

    const float* qb = q  + (size_t)bh*Lq*Dq;
    const float* kb = kk + ((size_t)bh*Lq + tile*128)*Dq;

    for (int i = t; i < Uq*16; i += 320) {
        int r = i >> 4, c4 = i & 15;
        float4 val = *(const float4*)(qb + (size_t)g_top[bh*Uq + r]*Dq + c4*4);
        *(float4*)&qs[r][c4*4] = val;
    }
    for (int i = t; i < 128*16; i += 320) {
        int l = i >> 4, c4 = i & 15;
        *(float4*)&ks[l][c4*4] = ((const float4*)(kb + (size_t)l*Dq))[c4];
    }
    __syncthreads();

    float acc[4][4] = {};
    #pragma unroll 4
    for (int c = 0; c < 64; c += 4) {
        float4 kr[4], qr[4];
        #pragma unroll
        for (int j = 0; j < 4; ++j) kr[j] = *(const float4*)&ks[lane + 32*j][c];
        #pragma unroll
        for (int j = 0; j < 4; ++j) qr[j] = *(const float4*)&qs[4*w + j][c];
        #pragma unroll
        for (int ji = 0; ji < 4; ++ji)
            #pragma unroll
            for (int jl = 0; jl < 4; ++jl) {
                acc[ji][jl] = fmaf(qr[ji].x, kr[jl].x, acc[ji][jl]);
                acc[ji][jl] = fmaf(qr[ji].y, kr[jl].y, acc[ji][jl]);
                acc[ji][jl] = fmaf(qr[ji].z, kr[jl].z, acc[ji][jl]);
                acc[ji][jl] = fmaf(qr[ji].w, kr[jl].w, acc[ji][jl]);
            }
    }
    #pragma unroll
    for (int ji = 0; ji < 4; ++ji) {
        int i = 4*w + ji;
        #pragma unroll
        for (int jl = 0; jl < 4; ++jl)
            attn[((size_t)bh*Uq + i)*Lq + tile*128 + lane + 32*jl] = acc[ji][jl] * 0.125f;
    }
}

// ---------------------------------------------------------------------------
// Kernel 4: row softmax (unchanged)
// ---------------------------------------------------------------------------
__global__ void k_softmax(float* __restrict__ attn) {
    __shared__ float red[256];
    int row = blockIdx.x, t = threadIdx.x;
    float* a = attn + (size_t)row * Lq;

    float4 v0 = ((float4*)a)[t];
    float4 v1 = ((float4*)a)[t + 256];

    float mx = fmaxf(fmaxf(fmaxf(v0.x, v0.y), fmaxf(v0.z, v0.w)),
                     fmaxf(fmaxf(v1.x, v1.y), fmaxf(v1.z, v1.w)));
    red[t] = mx; __syncthreads();
    for (int o = 128; o > 0; o >>= 1) { if (t < o) red[t] = fmaxf(red[t], red[t+o]); __syncthreads(); }
    mx = red[0]; __syncthreads();

    v0.x = expf(v0.x - mx); v0.y = expf(v0.y - mx);
    v0.z = expf(v0.z - mx); v0.w = expf(v0.w - mx);
    v1.x = expf(v1.x - mx); v1.y = expf(v1.y - mx);
    v1.z = expf(v1.z - mx); v1.w = expf(v1.w - mx);

    float s = v0.x + v0.y + v0.z + v0.w + v1.x + v1.y + v1.z + v1.w;
    red[t] = s; __syncthreads();
    for (int o = 128; o > 0; o >>= 1) { if (t < o) red[t] += red[t+o]; __syncthreads(); }
    float inv = 1.0f / red[0];

    v0.x *= inv; v0.y *= inv; v0.z *= inv; v0.w *= inv;
    v1.x *= inv; v1.y *= inv; v1.z *= inv; v1.w *= inv;
    ((float4*)a)[t]       = v0;
    ((float4*)a)[t + 256] = v1;
}

// ---------------------------------------------------------------------------
// Kernel 5: context partials, register-tiled (unchanged from R4)
// ---------------------------------------------------------------------------
__global__ __launch_bounds__(320) void k_ctx(const float* __restrict__ v,
                                             const float* __restrict__ attn) {
    __shared__ float2 vs2[64][32];
    __shared__ float  as_t[64][44];
    int bh = blockIdx.y, ch = blockIdx.x, t = threadIdx.x;
    int w = t >> 5, lane = t & 31;

    float2 c0 = {0.f,0.f}, c1 = {0.f,0.f}, c2 = {0.f,0.f}, c3 = {0.f,0.f};

    for (int tl = 0; tl < 4; ++tl) {
        int l0 = ch*256 + tl*64;
        for (int i = t; i < 64*16; i += 320) {
            int k = i >> 4, c4 = i & 15;
            *(float4*)((float*)&vs2[k][0] + c4*4) =
                ((const float4*)(v + ((size_t)bh*Lq + l0 + k)*Dq))[c4];
        }
        for (int i = t; i < Uq*64; i += 320) {
            int r = i >> 6, k = i & 63;
            as_t[k][r] = attn[((size_t)bh*Uq + r)*Lq + l0 + k];
        }
        __syncthreads();

        #pragma unroll 4
        for (int k = 0; k < 64; ++k) {
            float4 av = *(const float4*)&as_t[k][4*w];
            float2 vv = vs2[k][lane];
            c0.x = fmaf(av.x, vv.x, c0.x); c0.y = fmaf(av.x, vv.y, c0.y);
            c1.x = fmaf(av.y, vv.x, c1.x); c1.y = fmaf(av.y, vv.y, c1.y);
            c2.x = fmaf(av.z, vv.x, c2.x); c2.y = fmaf(av.z, vv.y, c2.y);
            c3.x = fmaf(av.w, vv.x, c3.x); c3.y = fmaf(av.w, vv.y, c3.y);
        }
        __syncthreads();
    }

    float* gp = g_part + (size_t)ch*CTXN + ((size_t)bh*Uq + 4*w)*Dq + 2*lane;
    *(float2*)(gp)          = c0;
    *(float2*)(gp + Dq)     = c1;
    *(float2*)(gp + 2*Dq)   = c2;
    *(float2*)(gp + 3*Dq)   = c3;
}

// ---------------------------------------------------------------------------
// Kernel 6: reduce the 8 partials (unchanged)
// ---------------------------------------------------------------------------
__global__ void k_reduce(float* __restrict__ ctx) {
    int i = blockIdx.x*256 + threadIdx.x;
    if (i < CTXN) {
        float s = 0.f;
        #pragma unroll
        for (int c = 0; c < NCH; ++c) s += g_part[(size_t)c*CTXN + i];
        ctx[i] = s;
    }
}

// ---------------------------------------------------------------------------
extern "C" void kernel_launch(void* const* d_in, const int* in_sizes, int n_in,
                              void* d_out, int out_size) {
    const float* q   = (const float*)d_in[0];
    const float* k   = (const float*)d_in[1];
    const float* v   = (const float*)d_in[2];
    const int*   idx = (const int*)d_in[3];

    float* ctx  = (float*)d_out;          // (B,H,u,D) = 163840 f32
    float* attn = ctx + CTXN;             // (B,H,u,L) = 5242880 f32

    const int smemM = 4096*sizeof(float4) + 8*Uq*sizeof(int);   // 66816 B
    cudaFuncSetAttribute(k_Mchunk, cudaFuncAttributeMaxDynamicSharedMemorySize, smemM);

    k_Mchunk<<<dim3(KCH, BH), 256, smemM>>>(q, k, idx);
    k_Mcomb<<<(BH*Lq)/256, 256>>>();
    k_topk<<<BH, 256>>>();
    k_scores<<<dim3(Lq/128, BH), 320>>>(q, k, attn);
    k_softmax<<<BH*Uq, 256>>>(attn);
    k_ctx<<<dim3(NCH, BH), 320>>>(v, attn);
    k_reduce<<<(CTXN + 255)/256, 256>>>(ctx);
}

// round 6
// speedup vs baseline: 2.6333x; 2.6333x over previous
#include <cuda_runtime.h>
#include <math.h>

#define Bq   8
#define Hq   8
#define Lq   2048
#define Dq   64
#define Uq   40
#define BH   64
#define CTXN (BH*Uq*Dq)
#define NCH  8

// scratch (no allocations allowed)
__device__ float g_M[BH*Lq];
__device__ int   g_top[BH*Uq];
__device__ float g_part[NCH*CTXN];

// ---------------------------------------------------------------------------
// Kernel 1: M[bh,l] = max_s(q·k[idx]) - sum_s(q·k[idx]) / L   (R4 proven)
// ---------------------------------------------------------------------------
__global__ __launch_bounds__(256) void k_M(const float* __restrict__ q,
                                           const float* __restrict__ kk,
                                           const int* __restrict__ idx) {
    int gw   = (blockIdx.x * blockDim.x + threadIdx.x) >> 5;   // bh*Lq + l
    int lane = threadIdx.x & 31;
    int g = lane >> 3;          // sample slot 0..3
    int e = lane & 7;           // 32B chunk 0..7
    int bh = gw >> 11;
    int l  = gw & (Lq - 1);

    const float*  kbase = kk + (size_t)bh*Lq*Dq;
    const float4* qrow  = (const float4*)(q + ((size_t)bh*Lq + l)*Dq);

    const float4 q0 = __ldg(qrow + 2*e);
    const float4 q1 = __ldg(qrow + 2*e + 1);

    const int* irow = idx + l*Uq;
    float mx = -INFINITY, sm = 0.f;

    #pragma unroll
    for (int i = 0; i < Uq/4; ++i) {
        int j = __ldg(irow + 4*i + g);
        const float4* kr = (const float4*)(kbase + (size_t)j*Dq);
        float4 a = __ldg(kr + 2*e);
        float4 b = __ldg(kr + 2*e + 1);
        float p = q0.x*a.x;
        p = fmaf(q0.y, a.y, p); p = fmaf(q0.z, a.z, p); p = fmaf(q0.w, a.w, p);
        p = fmaf(q1.x, b.x, p); p = fmaf(q1.y, b.y, p);
        p = fmaf(q1.z, b.z, p); p = fmaf(q1.w, b.w, p);
        p += __shfl_xor_sync(0xffffffffu, p, 4);
        p += __shfl_xor_sync(0xffffffffu, p, 2);
        p += __shfl_xor_sync(0xffffffffu, p, 1);
        mx = fmaxf(mx, p); sm += p;
    }
    mx = fmaxf(mx, __shfl_xor_sync(0xffffffffu, mx, 8));
    sm += __shfl_xor_sync(0xffffffffu, sm, 8);
    mx = fmaxf(mx, __shfl_xor_sync(0xffffffffu, mx, 16));
    sm += __shfl_xor_sync(0xffffffffu, sm, 16);

    if (lane == 0) g_M[gw] = mx - sm * (1.0f / (float)Lq);
}

// ---------------------------------------------------------------------------
// Kernel 2: top-40 per (bh), warp-shfl reduction (2 barriers/round, was 9).
// Ties -> lower index (jax order).
// ---------------------------------------------------------------------------
__global__ __launch_bounds__(256) void k_topk() {
    __shared__ float sv[Lq];
    __shared__ float rv[8];
    __shared__ int   ri[8];
    int bh = blockIdx.x, t = threadIdx.x;
    int w = t >> 5, lane = t & 31;

    for (int i = t; i < Lq; i += 256) sv[i] = g_M[bh*Lq + i];
    __syncthreads();

    for (int r = 0; r < Uq; ++r) {
        float bv = -INFINITY; int bi = Lq;
        #pragma unroll
        for (int ii = 0; ii < Lq/256; ++ii) {
            int i = t + 256*ii;
            float x = sv[i];
            if (x > bv || (x == bv && i < bi)) { bv = x; bi = i; }
        }
        #pragma unroll
        for (int o = 16; o > 0; o >>= 1) {
            float xv = __shfl_xor_sync(0xffffffffu, bv, o);
            int   xi = __shfl_xor_sync(0xffffffffu, bi, o);
            if (xv > bv || (xv == bv && xi < bi)) { bv = xv; bi = xi; }
        }
        if (lane == 0) { rv[w] = bv; ri[w] = bi; }
        __syncthreads();
        if (t == 0) {
            float fv = rv[0]; int fi = ri[0];
            #pragma unroll
            for (int j = 1; j < 8; ++j) {
                if (rv[j] > fv || (rv[j] == fv && ri[j] < fi)) { fv = rv[j]; fi = ri[j]; }
            }
            g_top[bh*Uq + r] = fi;
            sv[fi] = -INFINITY;
        }
        __syncthreads();
    }
}

// ---------------------------------------------------------------------------
// Kernel 3: scores, 5x4 register-tiled @ 256 threads (occupancy-tuned).
// warp w owns i-rows 5w..5w+4; lane owns l in {lane+32j}.
// ---------------------------------------------------------------------------
__global__ __launch_bounds__(256) void k_scores(const float* __restrict__ q,
                                                const float* __restrict__ kk,
                                                float* __restrict__ attn) {
    __shared__ float qs[Uq][68];     // 40x64, 68-word rows (16B-aligned, cf-free)
    __shared__ float ks[128][68];
    int bh = blockIdx.y, tile = blockIdx.x, t = threadIdx.x;
    int w = t >> 5, lane = t & 31;

    const float* qb = q  + (size_t)bh*Lq*Dq;
    const float* kb = kk + ((size_t)bh*Lq + tile*128)*Dq;

    for (int i = t; i < Uq*16; i += 256) {
        int r = i >> 4, c4 = i & 15;
        float4 val = *(const float4*)(qb + (size_t)g_top[bh*Uq + r]*Dq + c4*4);
        *(float4*)&qs[r][c4*4] = val;
    }
    for (int i = t; i < 128*16; i += 256) {
        int l = i >> 4, c4 = i & 15;
        *(float4*)&ks[l][c4*4] = ((const float4*)(kb + (size_t)l*Dq))[c4];
    }
    __syncthreads();

    float acc[5][4] = {};
    #pragma unroll 4
    for (int c = 0; c < 64; c += 4) {
        float4 kr[4];
        #pragma unroll
        for (int j = 0; j < 4; ++j) kr[j] = *(const float4*)&ks[lane + 32*j][c];
        #pragma unroll
        for (int ji = 0; ji < 5; ++ji) {
            float4 qr = *(const float4*)&qs[5*w + ji][c];   // warp broadcast
            #pragma unroll
            for (int jl = 0; jl < 4; ++jl) {
                acc[ji][jl] = fmaf(qr.x, kr[jl].x, acc[ji][jl]);
                acc[ji][jl] = fmaf(qr.y, kr[jl].y, acc[ji][jl]);
                acc[ji][jl] = fmaf(qr.z, kr[jl].z, acc[ji][jl]);
                acc[ji][jl] = fmaf(qr.w, kr[jl].w, acc[ji][jl]);
            }
        }
    }
    #pragma unroll
    for (int ji = 0; ji < 5; ++ji) {
        int i = 5*w + ji;
        #pragma unroll
        for (int jl = 0; jl < 4; ++jl)
            attn[((size_t)bh*Uq + i)*Lq + tile*128 + lane + 32*jl] = acc[ji][jl] * 0.125f;
    }
}

// ---------------------------------------------------------------------------
// Kernel 4: row softmax (unchanged)
// ---------------------------------------------------------------------------
__global__ void k_softmax(float* __restrict__ attn) {
    __shared__ float red[256];
    int row = blockIdx.x, t = threadIdx.x;
    float* a = attn + (size_t)row * Lq;

    float4 v0 = ((float4*)a)[t];
    float4 v1 = ((float4*)a)[t + 256];

    float mx = fmaxf(fmaxf(fmaxf(v0.x, v0.y), fmaxf(v0.z, v0.w)),
                     fmaxf(fmaxf(v1.x, v1.y), fmaxf(v1.z, v1.w)));
    red[t] = mx; __syncthreads();
    for (int o = 128; o > 0; o >>= 1) { if (t < o) red[t] = fmaxf(red[t], red[t+o]); __syncthreads(); }
    mx = red[0]; __syncthreads();

    v0.x = expf(v0.x - mx); v0.y = expf(v0.y - mx);
    v0.z = expf(v0.z - mx); v0.w = expf(v0.w - mx);
    v1.x = expf(v1.x - mx); v1.y = expf(v1.y - mx);
    v1.z = expf(v1.z - mx); v1.w = expf(v1.w - mx);

    float s = v0.x + v0.y + v0.z + v0.w + v1.x + v1.y + v1.z + v1.w;
    red[t] = s; __syncthreads();
    for (int o = 128; o > 0; o >>= 1) { if (t < o) red[t] += red[t+o]; __syncthreads(); }
    float inv = 1.0f / red[0];

    v0.x *= inv; v0.y *= inv; v0.z *= inv; v0.w *= inv;
    v1.x *= inv; v1.y *= inv; v1.z *= inv; v1.w *= inv;
    ((float4*)a)[t]       = v0;
    ((float4*)a)[t + 256] = v1;
}

// ---------------------------------------------------------------------------
// Kernel 5: context partials, register-tiled (R4 proven)
// ---------------------------------------------------------------------------
__global__ __launch_bounds__(320) void k_ctx(const float* __restrict__ v,
                                             const float* __restrict__ attn) {
    __shared__ float2 vs2[64][32];
    __shared__ float  as_t[64][44];
    int bh = blockIdx.y, ch = blockIdx.x, t = threadIdx.x;
    int w = t >> 5, lane = t & 31;

    float2 c0 = {0.f,0.f}, c1 = {0.f,0.f}, c2 = {0.f,0.f}, c3 = {0.f,0.f};

    for (int tl = 0; tl < 4; ++tl) {
        int l0 = ch*256 + tl*64;
        for (int i = t; i < 64*16; i += 320) {
            int k = i >> 4, c4 = i & 15;
            *(float4*)((float*)&vs2[k][0] + c4*4) =
                ((const float4*)(v + ((size_t)bh*Lq + l0 + k)*Dq))[c4];
        }
        for (int i = t; i < Uq*64; i += 320) {
            int r = i >> 6, k = i & 63;
            as_t[k][r] = attn[((size_t)bh*Uq + r)*Lq + l0 + k];
        }
        __syncthreads();

        #pragma unroll 4
        for (int k = 0; k < 64; ++k) {
            float4 av = *(const float4*)&as_t[k][4*w];
            float2 vv = vs2[k][lane];
            c0.x = fmaf(av.x, vv.x, c0.x); c0.y = fmaf(av.x, vv.y, c0.y);
            c1.x = fmaf(av.y, vv.x, c1.x); c1.y = fmaf(av.y, vv.y, c1.y);
            c2.x = fmaf(av.z, vv.x, c2.x); c2.y = fmaf(av.z, vv.y, c2.y);
            c3.x = fmaf(av.w, vv.x, c3.x); c3.y = fmaf(av.w, vv.y, c3.y);
        }
        __syncthreads();
    }

    float* gp = g_part + (size_t)ch*CTXN + ((size_t)bh*Uq + 4*w)*Dq + 2*lane;
    *(float2*)(gp)          = c0;
    *(float2*)(gp + Dq)     = c1;
    *(float2*)(gp + 2*Dq)   = c2;
    *(float2*)(gp + 3*Dq)   = c3;
}

// ---------------------------------------------------------------------------
// Kernel 6: reduce the 8 partials (unchanged)
// ---------------------------------------------------------------------------
__global__ void k_reduce(float* __restrict__ ctx) {
    int i = blockIdx.x*256 + threadIdx.x;
    if (i < CTXN) {
        float s = 0.f;
        #pragma unroll
        for (int c = 0; c < NCH; ++c) s += g_part[(size_t)c*CTXN + i];
        ctx[i] = s;
    }
}

// ---------------------------------------------------------------------------
extern "C" void kernel_launch(void* const* d_in, const int* in_sizes, int n_in,
                              void* d_out, int out_size) {
    const float* q   = (const float*)d_in[0];
    const float* k   = (const float*)d_in[1];
    const float* v   = (const float*)d_in[2];
    const int*   idx = (const int*)d_in[3];

    float* ctx  = (float*)d_out;          // (B,H,u,D) = 163840 f32
    float* attn = ctx + CTXN;             // (B,H,u,L) = 5242880 f32

    k_M<<<(BH*Lq*32)/256, 256>>>(q, k, idx);
    k_topk<<<BH, 256>>>();
    k_scores<<<dim3(Lq/128, BH), 256>>>(q, k, attn);
    k_softmax<<<BH*Uq, 256>>>(attn);
    k_ctx<<<dim3(NCH, BH), 320>>>(v, attn);
    k_reduce<<<(CTXN + 255)/256, 256>>>(ctx);
}

// round 8
// speedup vs baseline: 2.6461x; 1.0048x over previous
#include <cuda_runtime.h>
#include <cuda_pipeline.h>
#include <math.h>

#define Bq   8
#define Hq   8
#define Lq   2048
#define Dq   64
#define Uq   40
#define BH   64
#define CTXN (BH*Uq*Dq)
#define NCH  8

// scratch (no allocations allowed)
__device__ float g_M[BH*Lq];
__device__ int   g_top[BH*Uq];
__device__ float g_part[NCH*CTXN];

// ---------------------------------------------------------------------------
// Kernel 1: M[bh,l] = max_s(q·k[idx]) - sum_s(q·k[idx]) / L   (R4/R6 proven)
// ---------------------------------------------------------------------------
__global__ __launch_bounds__(256) void k_M(const float* __restrict__ q,
                                           const float* __restrict__ kk,
                                           const int* __restrict__ idx) {
    int gw   = (blockIdx.x * blockDim.x + threadIdx.x) >> 5;   // bh*Lq + l
    int lane = threadIdx.x & 31;
    int g = lane >> 3;          // sample slot 0..3
    int e = lane & 7;           // 32B chunk 0..7
    int bh = gw >> 11;
    int l  = gw & (Lq - 1);

    const float*  kbase = kk + (size_t)bh*Lq*Dq;
    const float4* qrow  = (const float4*)(q + ((size_t)bh*Lq + l)*Dq);

    const float4 q0 = __ldg(qrow + 2*e);
    const float4 q1 = __ldg(qrow + 2*e + 1);

    const int* irow = idx + l*Uq;
    float mx = -INFINITY, sm = 0.f;

    #pragma unroll
    for (int i = 0; i < Uq/4; ++i) {
        int j = __ldg(irow + 4*i + g);
        const float4* kr = (const float4*)(kbase + (size_t)j*Dq);
        float4 a = __ldg(kr + 2*e);
        float4 b = __ldg(kr + 2*e + 1);
        float p = q0.x*a.x;
        p = fmaf(q0.y, a.y, p); p = fmaf(q0.z, a.z, p); p = fmaf(q0.w, a.w, p);
        p = fmaf(q1.x, b.x, p); p = fmaf(q1.y, b.y, p);
        p = fmaf(q1.z, b.z, p); p = fmaf(q1.w, b.w, p);
        p += __shfl_xor_sync(0xffffffffu, p, 4);
        p += __shfl_xor_sync(0xffffffffu, p, 2);
        p += __shfl_xor_sync(0xffffffffu, p, 1);
        mx = fmaxf(mx, p); sm += p;
    }
    mx = fmaxf(mx, __shfl_xor_sync(0xffffffffu, mx, 8));
    sm += __shfl_xor_sync(0xffffffffu, sm, 8);
    mx = fmaxf(mx, __shfl_xor_sync(0xffffffffu, mx, 16));
    sm += __shfl_xor_sync(0xffffffffu, sm, 16);

    if (lane == 0) g_M[gw] = mx - sm * (1.0f / (float)Lq);
}

// ---------------------------------------------------------------------------
// Kernel 2: top-40 per (bh), warp-shfl reduction (R6 proven)
// ---------------------------------------------------------------------------
__global__ __launch_bounds__(256) void k_topk() {
    __shared__ float sv[Lq];
    __shared__ float rv[8];
    __shared__ int   ri[8];
    int bh = blockIdx.x, t = threadIdx.x;
    int w = t >> 5, lane = t & 31;

    for (int i = t; i < Lq; i += 256) sv[i] = g_M[bh*Lq + i];
    __syncthreads();

    for (int r = 0; r < Uq; ++r) {
        float bv = -INFINITY; int bi = Lq;
        #pragma unroll
        for (int ii = 0; ii < Lq/256; ++ii) {
            int i = t + 256*ii;
            float x = sv[i];
            if (x > bv || (x == bv && i < bi)) { bv = x; bi = i; }
        }
        #pragma unroll
        for (int o = 16; o > 0; o >>= 1) {
            float xv = __shfl_xor_sync(0xffffffffu, bv, o);
            int   xi = __shfl_xor_sync(0xffffffffu, bi, o);
            if (xv > bv || (xv == bv && xi < bi)) { bv = xv; bi = xi; }
        }
        if (lane == 0) { rv[w] = bv; ri[w] = bi; }
        __syncthreads();
        if (t == 0) {
            float fv = rv[0]; int fi = ri[0];
            #pragma unroll
            for (int j = 1; j < 8; ++j) {
                if (rv[j] > fv || (rv[j] == fv && ri[j] < fi)) { fv = rv[j]; fi = ri[j]; }
            }
            g_top[bh*Uq + r] = fi;
            sv[fi] = -INFINITY;
        }
        __syncthreads();
    }
}

// ---------------------------------------------------------------------------
// Kernel 3: scores, 5x4 register-tiled @ 256 threads (R6 proven)
// ---------------------------------------------------------------------------
__global__ __launch_bounds__(256) void k_scores(const float* __restrict__ q,
                                                const float* __restrict__ kk,
                                                float* __restrict__ attn) {
    __shared__ float qs[Uq][68];
    __shared__ float ks[128][68];
    int bh = blockIdx.y, tile = blockIdx.x, t = threadIdx.x;
    int w = t >> 5, lane = t & 31;

    const float* qb = q  + (size_t)bh*Lq*Dq;
    const float* kb = kk + ((size_t)bh*Lq + tile*128)*Dq;

    for (int i = t; i < Uq*16; i += 256) {
        int r = i >> 4, c4 = i & 15;
        float4 val = *(const float4*)(qb + (size_t)g_top[bh*Uq + r]*Dq + c4*4);
        *(float4*)&qs[r][c4*4] = val;
    }
    for (int i = t; i < 128*16; i += 256) {
        int l = i >> 4, c4 = i & 15;
        *(float4*)&ks[l][c4*4] = ((const float4*)(kb + (size_t)l*Dq))[c4];
    }
    __syncthreads();

    float acc[5][4] = {};
    #pragma unroll 4
    for (int c = 0; c < 64; c += 4) {
        float4 kr[4];
        #pragma unroll
        for (int j = 0; j < 4; ++j) kr[j] = *(const float4*)&ks[lane + 32*j][c];
        #pragma unroll
        for (int ji = 0; ji < 5; ++ji) {
            float4 qr = *(const float4*)&qs[5*w + ji][c];
            #pragma unroll
            for (int jl = 0; jl < 4; ++jl) {
                acc[ji][jl] = fmaf(qr.x, kr[jl].x, acc[ji][jl]);
                acc[ji][jl] = fmaf(qr.y, kr[jl].y, acc[ji][jl]);
                acc[ji][jl] = fmaf(qr.z, kr[jl].z, acc[ji][jl]);
                acc[ji][jl] = fmaf(qr.w, kr[jl].w, acc[ji][jl]);
            }
        }
    }
    #pragma unroll
    for (int ji = 0; ji < 5; ++ji) {
        int i = 5*w + ji;
        #pragma unroll
        for (int jl = 0; jl < 4; ++jl)
            attn[((size_t)bh*Uq + i)*Lq + tile*128 + lane + 32*jl] = acc[ji][jl] * 0.125f;
    }
}

// ---------------------------------------------------------------------------
// Kernel 4: row softmax, shfl reductions (3 barriers, was 16)
// ---------------------------------------------------------------------------
__global__ __launch_bounds__(256) void k_softmax(float* __restrict__ attn) {
    __shared__ float wred[8];
    int row = blockIdx.x, t = threadIdx.x;
    int w = t >> 5, lane = t & 31;
    float* a = attn + (size_t)row * Lq;

    float4 v0 = ((float4*)a)[t];
    float4 v1 = ((float4*)a)[t + 256];

    float mx = fmaxf(fmaxf(fmaxf(v0.x, v0.y), fmaxf(v0.z, v0.w)),
                     fmaxf(fmaxf(v1.x, v1.y), fmaxf(v1.z, v1.w)));
    #pragma unroll
    for (int o = 16; o > 0; o >>= 1) mx = fmaxf(mx, __shfl_xor_sync(0xffffffffu, mx, o));
    if (lane == 0) wred[w] = mx;
    __syncthreads();
    mx = wred[0];
    #pragma unroll
    for (int j = 1; j < 8; ++j) mx = fmaxf(mx, wred[j]);
    __syncthreads();                     // protect wred before sum reuse

    v0.x = expf(v0.x - mx); v0.y = expf(v0.y - mx);
    v0.z = expf(v0.z - mx); v0.w = expf(v0.w - mx);
    v1.x = expf(v1.x - mx); v1.y = expf(v1.y - mx);
    v1.z = expf(v1.z - mx); v1.w = expf(v1.w - mx);

    float s = v0.x + v0.y + v0.z + v0.w + v1.x + v1.y + v1.z + v1.w;
    #pragma unroll
    for (int o = 16; o > 0; o >>= 1) s += __shfl_xor_sync(0xffffffffu, s, o);
    if (lane == 0) wred[w] = s;
    __syncthreads();
    s = wred[0];
    #pragma unroll
    for (int j = 1; j < 8; ++j) s += wred[j];
    float inv = 1.0f / s;

    v0.x *= inv; v0.y *= inv; v0.z *= inv; v0.w *= inv;
    v1.x *= inv; v1.y *= inv; v1.z *= inv; v1.w *= inv;
    ((float4*)a)[t]       = v0;
    ((float4*)a)[t + 256] = v1;
}

// ---------------------------------------------------------------------------
// k_ctx tile fill via cp.async (pipeline intrinsics — parser-safe)
// ---------------------------------------------------------------------------
__device__ __forceinline__ void ctx_fill(float* vdst, float* adst,
                                         const float* __restrict__ vb,
                                         const float* __restrict__ ab,
                                         int l0, int t) {
    for (int i = t; i < 1024; i += 320) {          // V: 64 rows x 16 f4
        int k = i >> 4, c4 = i & 15;
        __pipeline_memcpy_async(vdst + (size_t)k*64 + c4*4,
                                vb + (size_t)(l0 + k)*Dq + c4*4, 16);
    }
    for (int i = t; i < 640; i += 320) {           // attn: 40 rows x 16 f4
        int r = i >> 4, c4 = i & 15;
        __pipeline_memcpy_async(adst + (size_t)r*64 + c4*4,
                                ab + (size_t)r*Lq + l0 + c4*4, 16);
    }
    __pipeline_commit();
}

// ---------------------------------------------------------------------------
// Kernel 5: context partials, cp.async double-buffered pipeline.
// Block=(ch, bh), 320 threads. V tile raw [64][64]; attn tile raw [40][64]
// (no transpose pass). warp w owns i-rows 4w..4w+3; lane owns d-pair.
// ---------------------------------------------------------------------------
__global__ __launch_bounds__(320) void k_ctx(const float* __restrict__ v,
                                             const float* __restrict__ attn) {
    extern __shared__ float smc[];
    float* vsm0 = smc;                 // 64*64
    float* vsm1 = smc + 4096;
    float* a_sm0 = smc + 8192;         // 40*64
    float* a_sm1 = smc + 8192 + 2560;
    int bh = blockIdx.y, ch = blockIdx.x, t = threadIdx.x;
    int w = t >> 5, lane = t & 31;

    const float* vb = v    + (size_t)bh*Lq*Dq;
    const float* ab = attn + (size_t)bh*Uq*Lq;

    float2 c0 = {0.f,0.f}, c1 = {0.f,0.f}, c2 = {0.f,0.f}, c3 = {0.f,0.f};

    ctx_fill(vsm0, a_sm0, vb, ab, ch*256, t);

    #pragma unroll
    for (int tl = 0; tl < 4; ++tl) {
        if (tl < 3) {
            ctx_fill((tl & 1) ? vsm0 : vsm1, (tl & 1) ? a_sm0 : a_sm1,
                     vb, ab, ch*256 + (tl+1)*64, t);
            __pipeline_wait_prior(1);
        } else {
            __pipeline_wait_prior(0);
        }
        __syncthreads();
        const float* vs = (tl & 1) ? vsm1 : vsm0;
        const float* as = (tl & 1) ? a_sm1 : a_sm0;
        #pragma unroll 4
        for (int k = 0; k < 64; ++k) {
            float a0 = as[(4*w+0)*64 + k];       // LDS.32 broadcast
            float a1 = as[(4*w+1)*64 + k];
            float a2 = as[(4*w+2)*64 + k];
            float a3 = as[(4*w+3)*64 + k];
            float2 vv = *(const float2*)&vs[(size_t)k*64 + 2*lane];  // cf-free
            c0.x = fmaf(a0, vv.x, c0.x); c0.y = fmaf(a0, vv.y, c0.y);
            c1.x = fmaf(a1, vv.x, c1.x); c1.y = fmaf(a1, vv.y, c1.y);
            c2.x = fmaf(a2, vv.x, c2.x); c2.y = fmaf(a2, vv.y, c2.y);
            c3.x = fmaf(a3, vv.x, c3.x); c3.y = fmaf(a3, vv.y, c3.y);
        }
        __syncthreads();   // buffer consumed before refill at tl+2
    }

    float* gp = g_part + (size_t)ch*CTXN + ((size_t)bh*Uq + 4*w)*Dq + 2*lane;
    *(float2*)(gp)          = c0;
    *(float2*)(gp + Dq)     = c1;
    *(float2*)(gp + 2*Dq)   = c2;
    *(float2*)(gp + 3*Dq)   = c3;
}

// ---------------------------------------------------------------------------
// Kernel 6: reduce the 8 partials (unchanged)
// ---------------------------------------------------------------------------
__global__ void k_reduce(float* __restrict__ ctx) {
    int i = blockIdx.x*256 + threadIdx.x;
    if (i < CTXN) {
        float s = 0.f;
        #pragma unroll
        for (int c = 0; c < NCH; ++c) s += g_part[(size_t)c*CTXN + i];
        ctx[i] = s;
    }
}

// ---------------------------------------------------------------------------
extern "C" void kernel_launch(void* const* d_in, const int* in_sizes, int n_in,
                              void* d_out, int out_size) {
    const float* q   = (const float*)d_in[0];
    const float* k   = (const float*)d_in[1];
    const float* v   = (const float*)d_in[2];
    const int*   idx = (const int*)d_in[3];

    float* ctx  = (float*)d_out;          // (B,H,u,D) = 163840 f32
    float* attn = ctx + CTXN;             // (B,H,u,L) = 5242880 f32

    const int smemCtx = (2*64*64 + 2*Uq*64) * sizeof(float);   // 53248 B
    cudaFuncSetAttribute(k_ctx, cudaFuncAttributeMaxDynamicSharedMemorySize, smemCtx);

    k_M<<<(BH*Lq*32)/256, 256>>>(q, k, idx);
    k_topk<<<BH, 256>>>();
    k_scores<<<dim3(Lq/128, BH), 256>>>(q, k, attn);
    k_softmax<<<BH*Uq, 256>>>(attn);
    k_ctx<<<dim3(NCH, BH), 320, smemCtx>>>(v, attn);
    k_reduce<<<(CTXN + 255)/256, 256>>>(ctx);
}